// round 1
// baseline (speedup 1.0000x reference)
#include <cuda_runtime.h>
#include <cuda_bf16.h>

#define E_EDGES 500000
#define HID_N   256
#define KDIM    512
#define TILE_M  128
#define KC      16
#define NCHUNK  (KDIM / KC)   // 32

// Fused: out[e] = b2 + sum_j relu( b1[j] + sum_k A[e][k]*W1[k][j] ) * W2[j]
// A[e][k] = k<256 ? emb_src[src[e]][k] : emb_dst[dst[e]][k-256]
__global__ __launch_bounds__(256, 1)
void linkpred_fused_kernel(const float* __restrict__ emb_src,
                           const float* __restrict__ emb_dst,
                           const int*   __restrict__ eidx,   // [2, E]
                           const float* __restrict__ W1,     // [512, 256]
                           const float* __restrict__ b1,     // [256]
                           const float* __restrict__ W2,     // [256]
                           const float* __restrict__ b2,     // [1]
                           float*       __restrict__ out)    // [E]
{
    __shared__ float As[2][KC][TILE_M];   // 16 KB  (A transposed: [k][m])
    __shared__ float Bs[2][KC][HID_N];    // 32 KB
    // total 48 KB static shared

    const int t  = threadIdx.x;
    const int tx = t & 15;    // column-thread  (16 cols, interleaved by 64)
    const int ty = t >> 4;    // row-thread     (8 rows each)
    const int m0 = blockIdx.x * TILE_M;

    // ---- A loader: threads 0..127 own one edge each (64B contiguous per chunk)
    const float* arow_src = emb_src;
    const float* arow_dst = emb_dst;
    if (t < TILE_M) {
        int mg = m0 + t;
        int mc = (mg < E_EDGES) ? mg : (E_EDGES - 1);
        int si = eidx[mc];
        int di = eidx[E_EDGES + mc];
        arow_src = emb_src + (size_t)si * HID_N;
        arow_dst = emb_dst + (size_t)di * HID_N;
    }
    // ---- B loader: all 256 threads, row bk, 4 x float4 at col bc + 64q
    const int bk = t >> 4;
    const int bc = (t & 15) * 4;

    float4 aR[4];
    float4 bR[4];

    auto gload = [&](int ch) {
        const int kbase = ch * KC;
        if (t < TILE_M) {
            const float* rp = ((kbase < HID_N) ? arow_src : arow_dst) + (kbase & (HID_N - 1));
            aR[0] = *(const float4*)(rp + 0);
            aR[1] = *(const float4*)(rp + 4);
            aR[2] = *(const float4*)(rp + 8);
            aR[3] = *(const float4*)(rp + 12);
        }
        const float* wrow = W1 + (size_t)(kbase + bk) * HID_N + bc;
        bR[0] = *(const float4*)(wrow + 0);
        bR[1] = *(const float4*)(wrow + 64);
        bR[2] = *(const float4*)(wrow + 128);
        bR[3] = *(const float4*)(wrow + 192);
    };
    auto stores = [&](int buf) {
        if (t < TILE_M) {
            #pragma unroll
            for (int q = 0; q < 4; q++) {
                As[buf][q * 4 + 0][t] = aR[q].x;
                As[buf][q * 4 + 1][t] = aR[q].y;
                As[buf][q * 4 + 2][t] = aR[q].z;
                As[buf][q * 4 + 3][t] = aR[q].w;
            }
        }
        #pragma unroll
        for (int q = 0; q < 4; q++)
            *(float4*)&Bs[buf][bk][bc + 64 * q] = bR[q];
    };

    float acc[8][16];
    #pragma unroll
    for (int i = 0; i < 8; i++)
        #pragma unroll
        for (int j = 0; j < 16; j++) acc[i][j] = 0.0f;

    gload(0);
    stores(0);
    __syncthreads();

    for (int ch = 0; ch < NCHUNK; ch++) {
        const int buf = ch & 1;
        if (ch + 1 < NCHUNK) gload(ch + 1);   // overlap next-chunk GMEM with compute

        #pragma unroll 4
        for (int k = 0; k < KC; k++) {
            float4 a0 = *(const float4*)&As[buf][k][ty * 8];
            float4 a1 = *(const float4*)&As[buf][k][ty * 8 + 4];
            float4 w0 = *(const float4*)&Bs[buf][k][tx * 4];
            float4 w1 = *(const float4*)&Bs[buf][k][tx * 4 + 64];
            float4 w2 = *(const float4*)&Bs[buf][k][tx * 4 + 128];
            float4 w3 = *(const float4*)&Bs[buf][k][tx * 4 + 192];
            float av[8]  = {a0.x, a0.y, a0.z, a0.w, a1.x, a1.y, a1.z, a1.w};
            float bv[16] = {w0.x, w0.y, w0.z, w0.w,
                            w1.x, w1.y, w1.z, w1.w,
                            w2.x, w2.y, w2.z, w2.w,
                            w3.x, w3.y, w3.z, w3.w};
            #pragma unroll
            for (int i = 0; i < 8; i++)
                #pragma unroll
                for (int j = 0; j < 16; j++)
                    acc[i][j] = fmaf(av[i], bv[j], acc[i][j]);
        }
        __syncthreads();
        if (ch + 1 < NCHUNK) {
            stores(buf ^ 1);
            __syncthreads();
        }
    }

    // ---- fused epilogue: relu(acc + b1) * W2, reduce over 16 column-threads
    float b1v[16], w2v[16];
    #pragma unroll
    for (int j = 0; j < 16; j++) {
        const int c = tx * 4 + (j & 3) + 64 * (j >> 2);
        b1v[j] = b1[c];
        w2v[j] = W2[c];
    }
    const float bias2 = b2[0];

    #pragma unroll
    for (int i = 0; i < 8; i++) {
        float s = 0.0f;
        #pragma unroll
        for (int j = 0; j < 16; j++) {
            float v = acc[i][j] + b1v[j];
            v = (v > 0.0f) ? v : 0.0f;
            s = fmaf(v, w2v[j], s);
        }
        // reduce over tx (lanes 0..15 / 16..31 within the warp)
        #pragma unroll
        for (int off = 8; off >= 1; off >>= 1)
            s += __shfl_xor_sync(0xffffffffu, s, off);
        if (tx == 0) {
            const int mg = m0 + ty * 8 + i;
            if (mg < E_EDGES) out[mg] = s + bias2;
        }
    }
}

extern "C" void kernel_launch(void* const* d_in, const int* in_sizes, int n_in,
                              void* d_out, int out_size) {
    const float* emb_src = (const float*)d_in[0];
    const float* emb_dst = (const float*)d_in[1];
    const int*   eidx    = (const int*)  d_in[2];
    const float* W1      = (const float*)d_in[3];
    const float* b1      = (const float*)d_in[4];
    const float* W2      = (const float*)d_in[5];
    const float* b2      = (const float*)d_in[6];
    float* out = (float*)d_out;

    const int grid = (E_EDGES + TILE_M - 1) / TILE_M;  // 3907
    linkpred_fused_kernel<<<grid, 256>>>(emb_src, emb_dst, eidx, W1, b1, W2, b2, out);
}

// round 3
// speedup vs baseline: 1.0161x; 1.0161x over previous
#include <cuda_runtime.h>
#include <cuda_bf16.h>

#define E_EDGES 500000
#define HID_N   256
#define KDIM    512
#define TILE_M  128
#define KC      16
#define NCHUNK  (KDIM / KC)   // 32

// Fused: out[e] = b2 + sum_j relu( b1[j] + sum_k A[e][k]*W1[k][j] ) * W2[j]
// A[e][k] = k<256 ? emb_src[src[e]][k] : emb_dst[dst[e]][k-256]

__device__ __forceinline__ unsigned long long pack2(float a, float b) {
    unsigned long long r;
    asm("mov.b64 %0, {%1, %2};" : "=l"(r) : "f"(a), "f"(b));
    return r;
}
__device__ __forceinline__ void unpack2(unsigned long long v, float& lo, float& hi) {
    asm("mov.b64 {%0, %1}, %2;" : "=f"(lo), "=f"(hi) : "l"(v));
}
__device__ __forceinline__ unsigned long long ffma2(unsigned long long a,
                                                    unsigned long long b,
                                                    unsigned long long c) {
    unsigned long long d;
    asm("fma.rn.f32x2 %0, %1, %2, %3;" : "=l"(d) : "l"(a), "l"(b), "l"(c));
    return d;
}

__global__ __launch_bounds__(256, 1)
void linkpred_fused_kernel(const float* __restrict__ emb_src,
                           const float* __restrict__ emb_dst,
                           const int*   __restrict__ eidx,   // [2, E]
                           const float* __restrict__ W1,     // [512, 256]
                           const float* __restrict__ b1,     // [256]
                           const float* __restrict__ W2,     // [256]
                           const float* __restrict__ b2,     // [1]
                           float*       __restrict__ out)    // [E]
{
    __shared__ __align__(16) float As[2][KC][TILE_M];   // 16 KB  (A transposed: [k][m])
    __shared__ __align__(16) float Bs[2][KC][HID_N];    // 32 KB

    const int t  = threadIdx.x;
    const int tx = t & 15;    // column-thread  (16 cols, interleaved by 64)
    const int ty = t >> 4;    // row-thread     (8 rows each)
    const int m0 = blockIdx.x * TILE_M;

    // ---- A loader: threads 0..127 own one edge each (64B contiguous per chunk)
    const float* arow_src = emb_src;
    const float* arow_dst = emb_dst;
    if (t < TILE_M) {
        int mg = m0 + t;
        int mc = (mg < E_EDGES) ? mg : (E_EDGES - 1);
        int si = eidx[mc];
        int di = eidx[E_EDGES + mc];
        arow_src = emb_src + (size_t)si * HID_N;
        arow_dst = emb_dst + (size_t)di * HID_N;
    }
    // ---- B loader: all 256 threads, row bk, 4 x float4 at col bc + 64q
    const int bk = t >> 4;
    const int bc = (t & 15) * 4;

    float4 aR[4];
    float4 bR[4];

    auto gload = [&](int ch) {
        const int kbase = ch * KC;
        if (t < TILE_M) {
            const float* rp = ((kbase < HID_N) ? arow_src : arow_dst) + (kbase & (HID_N - 1));
            aR[0] = *(const float4*)(rp + 0);
            aR[1] = *(const float4*)(rp + 4);
            aR[2] = *(const float4*)(rp + 8);
            aR[3] = *(const float4*)(rp + 12);
        }
        const float* wrow = W1 + (size_t)(kbase + bk) * HID_N + bc;
        bR[0] = *(const float4*)(wrow + 0);
        bR[1] = *(const float4*)(wrow + 64);
        bR[2] = *(const float4*)(wrow + 128);
        bR[3] = *(const float4*)(wrow + 192);
    };
    auto stores = [&](int buf) {
        if (t < TILE_M) {
            #pragma unroll
            for (int q = 0; q < 4; q++) {
                As[buf][q * 4 + 0][t] = aR[q].x;
                As[buf][q * 4 + 1][t] = aR[q].y;
                As[buf][q * 4 + 2][t] = aR[q].z;
                As[buf][q * 4 + 3][t] = aR[q].w;
            }
        }
        #pragma unroll
        for (int q = 0; q < 4; q++)
            *(float4*)&Bs[buf][bk][bc + 64 * q] = bR[q];
    };

    // packed accumulators: acc2[i][jp] holds cols {2*jp, 2*jp+1} of the old 16
    unsigned long long acc2[8][8];
    #pragma unroll
    for (int i = 0; i < 8; i++)
        #pragma unroll
        for (int jp = 0; jp < 8; jp++) acc2[i][jp] = 0ull;

    gload(0);
    stores(0);
    __syncthreads();

    for (int ch = 0; ch < NCHUNK; ch++) {
        const int buf = ch & 1;
        if (ch + 1 < NCHUNK) gload(ch + 1);   // overlap next-chunk GMEM with compute

        #pragma unroll 4
        for (int k = 0; k < KC; k++) {
            float4 a0 = *(const float4*)&As[buf][k][ty * 8];
            float4 a1 = *(const float4*)&As[buf][k][ty * 8 + 4];
            // B: 4 x LDS.128, each already two packed f32x2 operands
            ulonglong2 w01 = *(const ulonglong2*)&Bs[buf][k][tx * 4];
            ulonglong2 w23 = *(const ulonglong2*)&Bs[buf][k][tx * 4 + 64];
            ulonglong2 w45 = *(const ulonglong2*)&Bs[buf][k][tx * 4 + 128];
            ulonglong2 w67 = *(const ulonglong2*)&Bs[buf][k][tx * 4 + 192];
            unsigned long long bv2[8] = {w01.x, w01.y, w23.x, w23.y,
                                         w45.x, w45.y, w67.x, w67.y};
            float av[8] = {a0.x, a0.y, a0.z, a0.w, a1.x, a1.y, a1.z, a1.w};
            unsigned long long av2[8];
            #pragma unroll
            for (int i = 0; i < 8; i++) av2[i] = pack2(av[i], av[i]);
            #pragma unroll
            for (int i = 0; i < 8; i++)
                #pragma unroll
                for (int jp = 0; jp < 8; jp++)
                    acc2[i][jp] = ffma2(av2[i], bv2[jp], acc2[i][jp]);
        }
        __syncthreads();
        if (ch + 1 < NCHUNK) {
            stores(buf ^ 1);
            __syncthreads();
        }
    }

    // ---- fused epilogue: relu(acc + b1) * W2, reduce over 16 column-threads
    // packed pair jp covers cols: q = jp>>1, p = jp&1 -> c_lo = tx*4 + 2p + 64q
    float b1v[16], w2v[16];
    #pragma unroll
    for (int jp = 0; jp < 8; jp++) {
        const int c = tx * 4 + 2 * (jp & 1) + 64 * (jp >> 1);
        b1v[2 * jp]     = b1[c];
        b1v[2 * jp + 1] = b1[c + 1];
        w2v[2 * jp]     = W2[c];
        w2v[2 * jp + 1] = W2[c + 1];
    }
    const float bias2 = b2[0];

    #pragma unroll
    for (int i = 0; i < 8; i++) {
        float s = 0.0f;
        #pragma unroll
        for (int jp = 0; jp < 8; jp++) {
            float lo, hi;
            unpack2(acc2[i][jp], lo, hi);
            float v0 = lo + b1v[2 * jp];
            float v1 = hi + b1v[2 * jp + 1];
            v0 = (v0 > 0.0f) ? v0 : 0.0f;
            v1 = (v1 > 0.0f) ? v1 : 0.0f;
            s = fmaf(v0, w2v[2 * jp], s);
            s = fmaf(v1, w2v[2 * jp + 1], s);
        }
        // reduce over tx (lanes 0..15 / 16..31 within the warp)
        #pragma unroll
        for (int off = 8; off >= 1; off >>= 1)
            s += __shfl_xor_sync(0xffffffffu, s, off);
        if (tx == 0) {
            const int mg = m0 + ty * 8 + i;
            if (mg < E_EDGES) out[mg] = s + bias2;
        }
    }
}

extern "C" void kernel_launch(void* const* d_in, const int* in_sizes, int n_in,
                              void* d_out, int out_size) {
    const float* emb_src = (const float*)d_in[0];
    const float* emb_dst = (const float*)d_in[1];
    const int*   eidx    = (const int*)  d_in[2];
    const float* W1      = (const float*)d_in[3];
    const float* b1      = (const float*)d_in[4];
    const float* W2      = (const float*)d_in[5];
    const float* b2      = (const float*)d_in[6];
    float* out = (float*)d_out;

    const int grid = (E_EDGES + TILE_M - 1) / TILE_M;  // 3907
    linkpred_fused_kernel<<<grid, 256>>>(emb_src, emb_dst, eidx, W1, b1, W2, b2, out);
}

// round 6
// speedup vs baseline: 1.4979x; 1.4741x over previous
#include <cuda_runtime.h>
#include <cuda_fp16.h>
#include <cstdint>

#define E_EDGES 500000
#define HN      256
#define KDIM    512
#define TILE_M  128
#define KC      32
#define NCHUNKS (KDIM / KC)    // 16

// ---------------- device-global scratch (compile-time, no runtime alloc) ----
__device__ __align__(16) __half g_W1_hi[KDIM * HN];   // [k][n], same layout as W1
__device__ __align__(16) __half g_W1_lo[KDIM * HN];

// ---------------- prep: split W1 fp32 -> fp16 hi/lo --------------------------
__global__ void prep_w1_kernel(const float* __restrict__ W1) {
    int i = blockIdx.x * blockDim.x + threadIdx.x;
    if (i >= KDIM * HN) return;
    float w = W1[i];
    __half h = __float2half_rn(w);
    g_W1_hi[i] = h;
    g_W1_lo[i] = __float2half_rn(w - __half2float(h));
}

// ---------------- PTX helpers ------------------------------------------------
__device__ __forceinline__ uint32_t smem_u32(const void* p) {
    uint32_t a;
    asm("{ .reg .u64 t; cvta.to.shared.u64 t, %1; cvt.u32.u64 %0, t; }" : "=r"(a) : "l"(p));
    return a;
}

__device__ __forceinline__ void ldsm_x4(uint32_t addr, uint32_t& r0, uint32_t& r1,
                                        uint32_t& r2, uint32_t& r3) {
    asm volatile("ldmatrix.sync.aligned.m8n8.x4.shared.b16 {%0,%1,%2,%3}, [%4];"
                 : "=r"(r0), "=r"(r1), "=r"(r2), "=r"(r3) : "r"(addr));
}
__device__ __forceinline__ void ldsm_x4_t(uint32_t addr, uint32_t& r0, uint32_t& r1,
                                          uint32_t& r2, uint32_t& r3) {
    asm volatile("ldmatrix.sync.aligned.m8n8.x4.trans.shared.b16 {%0,%1,%2,%3}, [%4];"
                 : "=r"(r0), "=r"(r1), "=r"(r2), "=r"(r3) : "r"(addr));
}
__device__ __forceinline__ void mma16816(float* c, const uint32_t* a, uint32_t b0, uint32_t b1) {
    asm volatile(
        "mma.sync.aligned.m16n8k16.row.col.f32.f16.f16.f32 "
        "{%0,%1,%2,%3}, {%4,%5,%6,%7}, {%8,%9}, {%0,%1,%2,%3};"
        : "+f"(c[0]), "+f"(c[1]), "+f"(c[2]), "+f"(c[3])
        : "r"(a[0]), "r"(a[1]), "r"(a[2]), "r"(a[3]), "r"(b0), "r"(b1));
}

// ---------------- smem layout (dynamic) --------------------------------------
// As: [128 rows][32 halves], padded stride 40 halves (80B)  -> 10240 B per split
// Bs: [32 rows][256 halves], padded stride 264 halves (528B)-> 16896 B per split
#define A_STRIDE_B 80
#define B_STRIDE_B 528
#define SM_AHI 0
#define SM_ALO 10240
#define SM_BHI 20480
#define SM_BLO 37376
#define SM_DYN_BYTES 54272

__global__ __launch_bounds__(256, 1)
void linkpred_hmma_kernel(const float* __restrict__ emb_src,
                          const float* __restrict__ emb_dst,
                          const int*   __restrict__ eidx,
                          const float* __restrict__ b1,
                          const float* __restrict__ W2,
                          const float* __restrict__ b2,
                          float*       __restrict__ out)
{
    extern __shared__ char sm[];
    __shared__ float s_b1[HN], s_w2[HN];
    __shared__ float s_part[2][TILE_M];

    const int t    = threadIdx.x;
    const int lane = t & 31;
    const int wid  = t >> 5;
    const int wm   = wid & 3;    // 4 warps over M (32 rows each)
    const int wn   = wid >> 2;   // 2 warps over N (128 cols each)
    const int m0   = blockIdx.x * TILE_M;

    s_b1[t] = b1[t];
    s_w2[t] = W2[t];

    // ---- per-thread gather pointers (2 threads per edge row, 16 floats each)
    const int arow = t >> 1;
    const int aseg = t & 1;
    {
        // nothing else
    }
    int mg = m0 + arow;
    int mc = (mg < E_EDGES) ? mg : (E_EDGES - 1);
    const float* psrc = emb_src + (size_t)eidx[mc] * HN;
    const float* pdst = emb_dst + (size_t)eidx[E_EDGES + mc] * HN;

    // ---- B loader coords: thread -> (k-row, 32-half segment)
    const int bkrow = t >> 3;
    const int bnseg = (t & 7) * 32;   // halves

    const uint32_t smb = smem_u32(sm);

    // ldmatrix source addresses (constant across chunks except k-step offset)
    // A (row-major m16k16): lane l -> row (l&15), col-halves (l>>4)*8
    const uint32_t a_lrow = (uint32_t)(wm * 32 + (lane & 15));
    const uint32_t a_lcol = (uint32_t)((lane >> 4) * 8);     // halves
    // B (trans, [k][n]): lane l -> k-row (l&15), n-col +(l>>4)*8
    const uint32_t b_lrow = (uint32_t)(lane & 15);
    const uint32_t b_lcol = (uint32_t)(wn * 128 + (lane >> 4) * 8);  // halves

    float acc[2][16][4];
    #pragma unroll
    for (int f = 0; f < 2; f++)
        #pragma unroll
        for (int g = 0; g < 16; g++)
            #pragma unroll
            for (int c = 0; c < 4; c++) acc[f][g][c] = 0.0f;

    #pragma unroll 1
    for (int ch = 0; ch < NCHUNKS; ch++) {
        const int kbase = ch * KC;

        // ---- A: gather 16 fp32, split to fp16 hi/lo, store swiz-free padded
        {
            const float* rp = ((kbase < HN) ? (psrc + kbase) : (pdst + (kbase - HN)))
                              + aseg * 16;
            float4 v0 = __ldg((const float4*)(rp + 0));
            float4 v1 = __ldg((const float4*)(rp + 4));
            float4 v2 = __ldg((const float4*)(rp + 8));
            float4 v3 = __ldg((const float4*)(rp + 12));
            float f[16] = {v0.x, v0.y, v0.z, v0.w, v1.x, v1.y, v1.z, v1.w,
                           v2.x, v2.y, v2.z, v2.w, v3.x, v3.y, v3.z, v3.w};
            alignas(16) __half hs[16], ls[16];
            #pragma unroll
            for (int i = 0; i < 16; i++) {
                __half h = __float2half_rn(f[i]);
                hs[i] = h;
                ls[i] = __float2half_rn(f[i] - __half2float(h));
            }
            uint32_t off = (uint32_t)arow * A_STRIDE_B + aseg * 32;
            *(uint4*)(sm + SM_AHI + off)      = ((const uint4*)hs)[0];
            *(uint4*)(sm + SM_AHI + off + 16) = ((const uint4*)hs)[1];
            *(uint4*)(sm + SM_ALO + off)      = ((const uint4*)ls)[0];
            *(uint4*)(sm + SM_ALO + off + 16) = ((const uint4*)ls)[1];
        }
        // ---- B: copy one 64B segment of W1 hi/lo rows
        {
            const __half* gh = g_W1_hi + (size_t)(kbase + bkrow) * HN + bnseg;
            const __half* gl = g_W1_lo + (size_t)(kbase + bkrow) * HN + bnseg;
            uint32_t off = (uint32_t)bkrow * B_STRIDE_B + bnseg * 2;
            #pragma unroll
            for (int q = 0; q < 4; q++) {
                *(uint4*)(sm + SM_BHI + off + q * 16) = __ldg((const uint4*)gh + q);
                *(uint4*)(sm + SM_BLO + off + q * 16) = __ldg((const uint4*)gl + q);
            }
        }
        __syncthreads();

        // ---- compute: 2 k16 steps per chunk
        #pragma unroll
        for (int ks = 0; ks < 2; ks++) {
            uint32_t ah[2][4], al[2][4];
            #pragma unroll
            for (int f = 0; f < 2; f++) {
                uint32_t aaddr = smb + (a_lrow + f * 16) * A_STRIDE_B
                               + (ks * 16 + a_lcol) * 2;
                ldsm_x4(aaddr + SM_AHI, ah[f][0], ah[f][1], ah[f][2], ah[f][3]);
                ldsm_x4(aaddr + SM_ALO, al[f][0], al[f][1], al[f][2], al[f][3]);
            }
            #pragma unroll
            for (int g4 = 0; g4 < 8; g4++) {   // 8 groups of n16 per warp
                uint32_t baddr = smb + (ks * 16 + b_lrow) * B_STRIDE_B
                               + (b_lcol + g4 * 16) * 2;
                uint32_t bh0, bh1, bh2, bh3, bl0, bl1, bl2, bl3;
                ldsm_x4_t(baddr + SM_BHI, bh0, bh1, bh2, bh3);
                ldsm_x4_t(baddr + SM_BLO, bl0, bl1, bl2, bl3);
                #pragma unroll
                for (int f = 0; f < 2; f++) {
                    float* c0 = acc[f][g4 * 2];
                    float* c1 = acc[f][g4 * 2 + 1];
                    mma16816(c0, ah[f], bh0, bh1);   // hi*hi
                    mma16816(c0, ah[f], bl0, bl1);   // hi*lo
                    mma16816(c0, al[f], bh0, bh1);   // lo*hi
                    mma16816(c1, ah[f], bh2, bh3);
                    mma16816(c1, ah[f], bl2, bl3);
                    mma16816(c1, al[f], bh2, bh3);
                }
            }
        }
        __syncthreads();
    }

    // ---- fused epilogue: relu(acc + b1) * W2 -> per-row partial sums --------
    #pragma unroll
    for (int f = 0; f < 2; f++) {
        float s0 = 0.0f, s1 = 0.0f;
        #pragma unroll
        for (int g = 0; g < 16; g++) {
            const int col = wn * 128 + g * 8 + (lane & 3) * 2;
            const float b1a = s_b1[col],     b1b = s_b1[col + 1];
            const float w2a = s_w2[col],     w2b = s_w2[col + 1];
            float v;
            v = acc[f][g][0] + b1a; v = fmaxf(v, 0.0f); s0 = fmaf(v, w2a, s0);
            v = acc[f][g][1] + b1b; v = fmaxf(v, 0.0f); s0 = fmaf(v, w2b, s0);
            v = acc[f][g][2] + b1a; v = fmaxf(v, 0.0f); s1 = fmaf(v, w2a, s1);
            v = acc[f][g][3] + b1b; v = fmaxf(v, 0.0f); s1 = fmaf(v, w2b, s1);
        }
        // reduce over the 4 lanes sharing a row (different cols)
        s0 += __shfl_xor_sync(0xffffffffu, s0, 1);
        s0 += __shfl_xor_sync(0xffffffffu, s0, 2);
        s1 += __shfl_xor_sync(0xffffffffu, s1, 1);
        s1 += __shfl_xor_sync(0xffffffffu, s1, 2);
        if ((lane & 3) == 0) {
            const int r = wm * 32 + f * 16 + (lane >> 2);
            s_part[wn][r]     = s0;
            s_part[wn][r + 8] = s1;
        }
    }
    __syncthreads();

    if (t < TILE_M) {
        const int mgo = m0 + t;
        if (mgo < E_EDGES)
            out[mgo] = s_part[0][t] + s_part[1][t] + __ldg(b2);
    }
}

// ---------------- launch -----------------------------------------------------
extern "C" void kernel_launch(void* const* d_in, const int* in_sizes, int n_in,
                              void* d_out, int out_size) {
    const float* emb_src = (const float*)d_in[0];
    const float* emb_dst = (const float*)d_in[1];
    const int*   eidx    = (const int*)  d_in[2];
    const float* W1      = (const float*)d_in[3];
    const float* b1      = (const float*)d_in[4];
    const float* W2      = (const float*)d_in[5];
    const float* b2      = (const float*)d_in[6];
    float* out = (float*)d_out;

    static bool attr_done = false;
    if (!attr_done) {
        cudaFuncSetAttribute(linkpred_hmma_kernel,
                             cudaFuncAttributeMaxDynamicSharedMemorySize, SM_DYN_BYTES);
        attr_done = true;
    }

    prep_w1_kernel<<<(KDIM * HN + 255) / 256, 256>>>(W1);

    const int grid = (E_EDGES + TILE_M - 1) / TILE_M;   // 3907
    linkpred_hmma_kernel<<<grid, 256, SM_DYN_BYTES>>>(
        emb_src, emb_dst, eidx, b1, W2, b2, out);
}

// round 8
// speedup vs baseline: 2.0260x; 1.3526x over previous
#include <cuda_runtime.h>
#include <cuda_fp16.h>
#include <cstdint>

#define E_EDGES 500000
#define HN      256
#define KDIM    512
#define TILE_M  128
#define KC      32
#define NCHUNKS (KDIM / KC)    // 16

// ---------------- device-global scratch (compile-time, no runtime alloc) ----
__device__ __align__(16) __half g_W1_hi[KDIM * HN];   // [k][n], same layout as W1
__device__ __align__(16) __half g_W1_lo[KDIM * HN];

// ---------------- prep: split W1 fp32 -> fp16 hi/lo --------------------------
__global__ void prep_w1_kernel(const float* __restrict__ W1) {
    int i = blockIdx.x * blockDim.x + threadIdx.x;
    if (i >= KDIM * HN) return;
    float w = W1[i];
    __half h = __float2half_rn(w);
    g_W1_hi[i] = h;
    g_W1_lo[i] = __float2half_rn(w - __half2float(h));
}

// ---------------- PTX helpers ------------------------------------------------
__device__ __forceinline__ uint32_t smem_u32(const void* p) {
    uint32_t a;
    asm("{ .reg .u64 t; cvta.to.shared.u64 t, %1; cvt.u32.u64 %0, t; }" : "=r"(a) : "l"(p));
    return a;
}
__device__ __forceinline__ void ldsm_x4(uint32_t addr, uint32_t& r0, uint32_t& r1,
                                        uint32_t& r2, uint32_t& r3) {
    asm volatile("ldmatrix.sync.aligned.m8n8.x4.shared.b16 {%0,%1,%2,%3}, [%4];"
                 : "=r"(r0), "=r"(r1), "=r"(r2), "=r"(r3) : "r"(addr));
}
__device__ __forceinline__ void ldsm_x4_t(uint32_t addr, uint32_t& r0, uint32_t& r1,
                                          uint32_t& r2, uint32_t& r3) {
    asm volatile("ldmatrix.sync.aligned.m8n8.x4.trans.shared.b16 {%0,%1,%2,%3}, [%4];"
                 : "=r"(r0), "=r"(r1), "=r"(r2), "=r"(r3) : "r"(addr));
}
__device__ __forceinline__ void mma16816(float* c, const uint32_t* a, uint32_t b0, uint32_t b1) {
    asm volatile(
        "mma.sync.aligned.m16n8k16.row.col.f32.f16.f16.f32 "
        "{%0,%1,%2,%3}, {%4,%5,%6,%7}, {%8,%9}, {%0,%1,%2,%3};"
        : "+f"(c[0]), "+f"(c[1]), "+f"(c[2]), "+f"(c[3])
        : "r"(a[0]), "r"(a[1]), "r"(a[2]), "r"(a[3]), "r"(b0), "r"(b1));
}
__device__ __forceinline__ void cp_async16(uint32_t saddr, const void* gptr) {
    asm volatile("cp.async.cg.shared.global [%0], [%1], 16;" :: "r"(saddr), "l"(gptr));
}
#define CP_COMMIT() asm volatile("cp.async.commit_group;" ::: "memory")
#define CP_WAIT0()  asm volatile("cp.async.wait_group 0;"  ::: "memory")

// ---------------- smem layout: 2 stages of (Ahi|Alo|Bhi|Blo) -----------------
// As: [128][32h] stride 80B  -> 10240 B per split
// Bs: [32][256h] stride 528B -> 16896 B per split
#define A_STRIDE_B 80
#define B_STRIDE_B 528
#define SM_AHI 0
#define SM_ALO 10240
#define SM_BHI 20480
#define SM_BLO 37376
#define STAGE_B 54272
#define SM_DYN_BYTES (2 * STAGE_B)   // 108544

__global__ __launch_bounds__(256, 1)
void linkpred_hmma_kernel(const float* __restrict__ emb_src,
                          const float* __restrict__ emb_dst,
                          const int*   __restrict__ eidx,
                          const float* __restrict__ b1,
                          const float* __restrict__ W2,
                          const float* __restrict__ b2,
                          float*       __restrict__ out)
{
    extern __shared__ char sm[];
    __shared__ float s_b1[HN], s_w2[HN];
    __shared__ float s_part[2][TILE_M];

    const int t    = threadIdx.x;
    const int lane = t & 31;
    const int wid  = t >> 5;
    const int wm   = wid & 3;    // 4 warps over M (32 rows each)
    const int wn   = wid >> 2;   // 2 warps over N (128 cols each)
    const int m0   = blockIdx.x * TILE_M;

    s_b1[t] = b1[t];
    s_w2[t] = W2[t];

    // ---- A gather: 2 threads per edge row, 16 floats (64B) each
    const int arow = t >> 1;
    const int aseg = t & 1;
    int mg = m0 + arow;
    int mc = (mg < E_EDGES) ? mg : (E_EDGES - 1);
    const float* psrc = emb_src + (size_t)eidx[mc] * HN;
    const float* pdst = emb_dst + (size_t)eidx[E_EDGES + mc] * HN;

    // ---- B copy coords: thread -> (k-row, 32-half segment)
    const int bkrow = t >> 3;
    const int bnseg = (t & 7) * 32;   // halves

    const uint32_t smb = smem_u32(sm);

    // ldmatrix lane addressing
    const uint32_t a_lrow = (uint32_t)(wm * 32 + (lane & 15));
    const uint32_t a_lcol = (uint32_t)((lane >> 4) * 8);             // halves
    const uint32_t b_lrow = (uint32_t)(lane & 15);
    const uint32_t b_lcol = (uint32_t)(wn * 128 + (lane >> 4) * 8);  // halves

    float acc[2][16][4];
    #pragma unroll
    for (int f = 0; f < 2; f++)
        #pragma unroll
        for (int g = 0; g < 16; g++)
            #pragma unroll
            for (int c = 0; c < 4; c++) acc[f][g][c] = 0.0f;

    float4 aR[4];

    auto a_issue = [&](int ch) {
        const int kbase = ch * KC;
        const float* rp = ((kbase < HN) ? (psrc + kbase) : (pdst + (kbase - HN)))
                          + aseg * 16;
        aR[0] = __ldg((const float4*)(rp + 0));
        aR[1] = __ldg((const float4*)(rp + 4));
        aR[2] = __ldg((const float4*)(rp + 8));
        aR[3] = __ldg((const float4*)(rp + 12));
    };
    auto a_store = [&](int stage) {
        float f[16] = {aR[0].x, aR[0].y, aR[0].z, aR[0].w,
                       aR[1].x, aR[1].y, aR[1].z, aR[1].w,
                       aR[2].x, aR[2].y, aR[2].z, aR[2].w,
                       aR[3].x, aR[3].y, aR[3].z, aR[3].w};
        alignas(16) __half hs[16], ls[16];
        #pragma unroll
        for (int i = 0; i < 16; i++) {
            __half h = __float2half_rn(f[i]);
            hs[i] = h;
            ls[i] = __float2half_rn(f[i] - __half2float(h));
        }
        char* base = sm + stage * STAGE_B;
        uint32_t off = (uint32_t)arow * A_STRIDE_B + aseg * 32;
        *(uint4*)(base + SM_AHI + off)      = ((const uint4*)hs)[0];
        *(uint4*)(base + SM_AHI + off + 16) = ((const uint4*)hs)[1];
        *(uint4*)(base + SM_ALO + off)      = ((const uint4*)ls)[0];
        *(uint4*)(base + SM_ALO + off + 16) = ((const uint4*)ls)[1];
    };
    auto b_issue = [&](int ch, int stage) {
        const int kbase = ch * KC;
        const __half* gh = g_W1_hi + (size_t)(kbase + bkrow) * HN + bnseg;
        const __half* gl = g_W1_lo + (size_t)(kbase + bkrow) * HN + bnseg;
        uint32_t off = smb + stage * STAGE_B + (uint32_t)bkrow * B_STRIDE_B + bnseg * 2;
        #pragma unroll
        for (int q = 0; q < 4; q++) {
            cp_async16(off + SM_BHI + q * 16, gh + 8 * q);
            cp_async16(off + SM_BLO + q * 16, gl + 8 * q);
        }
    };
    auto compute = [&](int stage) {
        const uint32_t sbase = smb + stage * STAGE_B;
        #pragma unroll
        for (int ks = 0; ks < 2; ks++) {
            uint32_t ah[2][4], al[2][4];
            #pragma unroll
            for (int f = 0; f < 2; f++) {
                uint32_t aaddr = sbase + (a_lrow + f * 16) * A_STRIDE_B
                               + (ks * 16 + a_lcol) * 2;
                ldsm_x4(aaddr + SM_AHI, ah[f][0], ah[f][1], ah[f][2], ah[f][3]);
                ldsm_x4(aaddr + SM_ALO, al[f][0], al[f][1], al[f][2], al[f][3]);
            }
            #pragma unroll
            for (int g4 = 0; g4 < 8; g4++) {
                uint32_t baddr = sbase + (ks * 16 + b_lrow) * B_STRIDE_B
                               + (b_lcol + g4 * 16) * 2;
                uint32_t bh0, bh1, bh2, bh3, bl0, bl1, bl2, bl3;
                ldsm_x4_t(baddr + SM_BHI, bh0, bh1, bh2, bh3);
                ldsm_x4_t(baddr + SM_BLO, bl0, bl1, bl2, bl3);
                #pragma unroll
                for (int f = 0; f < 2; f++) {
                    float* c0 = acc[f][g4 * 2];
                    float* c1 = acc[f][g4 * 2 + 1];
                    mma16816(c0, ah[f], bh0, bh1);   // hi*hi
                    mma16816(c0, ah[f], bl0, bl1);   // hi*lo
                    mma16816(c0, al[f], bh0, bh1);   // lo*hi
                    mma16816(c1, ah[f], bh2, bh3);
                    mma16816(c1, ah[f], bl2, bl3);
                    mma16816(c1, al[f], bh2, bh3);
                }
            }
        }
    };

    // ---- prologue: fill stage 0
    a_issue(0);
    b_issue(0, 0);
    CP_COMMIT();
    a_store(0);
    CP_WAIT0();
    __syncthreads();

    // ---- 2-stage pipelined mainloop: one sync per chunk
    #pragma unroll 1
    for (int ch = 0; ch < NCHUNKS; ch++) {
        const int cur = ch & 1;
        const int nxt = cur ^ 1;
        if (ch + 1 < NCHUNKS) {
            a_issue(ch + 1);          // long-latency LDGs first
            b_issue(ch + 1, nxt);     // cp.async overlaps with MMAs below
            CP_COMMIT();
        }
        compute(cur);
        if (ch + 1 < NCHUNKS) {
            a_store(nxt);             // convert + STS after compute consumed cur
            CP_WAIT0();
        }
        __syncthreads();
    }

    // ---- fused epilogue: relu(acc + b1) * W2 -> per-row partial sums --------
    #pragma unroll
    for (int f = 0; f < 2; f++) {
        float s0 = 0.0f, s1 = 0.0f;
        #pragma unroll
        for (int g = 0; g < 16; g++) {
            const int col = wn * 128 + g * 8 + (lane & 3) * 2;
            const float b1a = s_b1[col], b1b = s_b1[col + 1];
            const float w2a = s_w2[col], w2b = s_w2[col + 1];
            float v;
            v = acc[f][g][0] + b1a; v = fmaxf(v, 0.0f); s0 = fmaf(v, w2a, s0);
            v = acc[f][g][1] + b1b; v = fmaxf(v, 0.0f); s0 = fmaf(v, w2b, s0);
            v = acc[f][g][2] + b1a; v = fmaxf(v, 0.0f); s1 = fmaf(v, w2a, s1);
            v = acc[f][g][3] + b1b; v = fmaxf(v, 0.0f); s1 = fmaf(v, w2b, s1);
        }
        s0 += __shfl_xor_sync(0xffffffffu, s0, 1);
        s0 += __shfl_xor_sync(0xffffffffu, s0, 2);
        s1 += __shfl_xor_sync(0xffffffffu, s1, 1);
        s1 += __shfl_xor_sync(0xffffffffu, s1, 2);
        if ((lane & 3) == 0) {
            const int r = wm * 32 + f * 16 + (lane >> 2);
            s_part[wn][r]     = s0;
            s_part[wn][r + 8] = s1;
        }
    }
    __syncthreads();

    if (t < TILE_M) {
        const int mgo = m0 + t;
        if (mgo < E_EDGES)
            out[mgo] = s_part[0][t] + s_part[1][t] + __ldg(b2);
    }
}

// ---------------- launch -----------------------------------------------------
extern "C" void kernel_launch(void* const* d_in, const int* in_sizes, int n_in,
                              void* d_out, int out_size) {
    const float* emb_src = (const float*)d_in[0];
    const float* emb_dst = (const float*)d_in[1];
    const int*   eidx    = (const int*)  d_in[2];
    const float* W1      = (const float*)d_in[3];
    const float* b1      = (const float*)d_in[4];
    const float* W2      = (const float*)d_in[5];
    const float* b2      = (const float*)d_in[6];
    float* out = (float*)d_out;

    static bool attr_done = false;
    if (!attr_done) {
        cudaFuncSetAttribute(linkpred_hmma_kernel,
                             cudaFuncAttributeMaxDynamicSharedMemorySize, SM_DYN_BYTES);
        attr_done = true;
    }

    prep_w1_kernel<<<(KDIM * HN + 255) / 256, 256>>>(W1);

    const int grid = (E_EDGES + TILE_M - 1) / TILE_M;   // 3907
    linkpred_hmma_kernel<<<grid, 256, SM_DYN_BYTES>>>(
        emb_src, emb_dst, eidx, b1, W2, b2, out);
}

// round 9
// speedup vs baseline: 2.5425x; 1.2549x over previous
#include <cuda_runtime.h>
#include <cuda_fp16.h>
#include <cstdint>

#define E_EDGES 500000
#define HN      256
#define KDIM    512
#define TILE_M  128
#define KC      32
#define NCHUNKS (KDIM / KC)    // 16

// ---------------- device-global scratch (compile-time, no runtime alloc) ----
__device__ __align__(16) __half g_W1_hi[KDIM * HN];   // [k][n], same layout as W1
__device__ __align__(16) __half g_W1_lo[KDIM * HN];

// ---------------- prep: split W1 fp32 -> fp16 hi/lo --------------------------
__global__ void prep_w1_kernel(const float* __restrict__ W1) {
    int i = blockIdx.x * blockDim.x + threadIdx.x;
    if (i >= KDIM * HN) return;
    float w = W1[i];
    __half h = __float2half_rn(w);
    g_W1_hi[i] = h;
    g_W1_lo[i] = __float2half_rn(w - __half2float(h));
}

// ---------------- PTX helpers ------------------------------------------------
__device__ __forceinline__ uint32_t smem_u32(const void* p) {
    uint32_t a;
    asm("{ .reg .u64 t; cvta.to.shared.u64 t, %1; cvt.u32.u64 %0, t; }" : "=r"(a) : "l"(p));
    return a;
}
__device__ __forceinline__ void ldsm_x4(uint32_t addr, uint32_t& r0, uint32_t& r1,
                                        uint32_t& r2, uint32_t& r3) {
    asm volatile("ldmatrix.sync.aligned.m8n8.x4.shared.b16 {%0,%1,%2,%3}, [%4];"
                 : "=r"(r0), "=r"(r1), "=r"(r2), "=r"(r3) : "r"(addr));
}
__device__ __forceinline__ void ldsm_x4_t(uint32_t addr, uint32_t& r0, uint32_t& r1,
                                          uint32_t& r2, uint32_t& r3) {
    asm volatile("ldmatrix.sync.aligned.m8n8.x4.trans.shared.b16 {%0,%1,%2,%3}, [%4];"
                 : "=r"(r0), "=r"(r1), "=r"(r2), "=r"(r3) : "r"(addr));
}
__device__ __forceinline__ void mma16816(float* c, const uint32_t* a, uint32_t b0, uint32_t b1) {
    asm volatile(
        "mma.sync.aligned.m16n8k16.row.col.f32.f16.f16.f32 "
        "{%0,%1,%2,%3}, {%4,%5,%6,%7}, {%8,%9}, {%0,%1,%2,%3};"
        : "+f"(c[0]), "+f"(c[1]), "+f"(c[2]), "+f"(c[3])
        : "r"(a[0]), "r"(a[1]), "r"(a[2]), "r"(a[3]), "r"(b0), "r"(b1));
}
__device__ __forceinline__ void cp_async16(uint32_t saddr, const void* gptr) {
    asm volatile("cp.async.cg.shared.global [%0], [%1], 16;" :: "r"(saddr), "l"(gptr));
}
#define CP_COMMIT() asm volatile("cp.async.commit_group;" ::: "memory")
#define CP_WAIT0()  asm volatile("cp.async.wait_group 0;"  ::: "memory")

// ---------------- smem layout: 2 stages of (Ahi|Bhi|Blo) ---------------------
// As: [128][32h] stride 80B  -> 10240 B
// Bs: [32][256h] stride 528B -> 16896 B per split
#define A_STRIDE_B 80
#define B_STRIDE_B 528
#define SM_AHI 0
#define SM_BHI 10240
#define SM_BLO 27136
#define STAGE_B 44032
#define SM_DYN_BYTES (2 * STAGE_B)   // 88064

__global__ __launch_bounds__(256, 1)
void linkpred_hmma_kernel(const float* __restrict__ emb_src,
                          const float* __restrict__ emb_dst,
                          const int*   __restrict__ eidx,
                          const float* __restrict__ b1,
                          const float* __restrict__ W2,
                          const float* __restrict__ b2,
                          float*       __restrict__ out)
{
    extern __shared__ char sm[];
    __shared__ float s_b1[HN], s_w2[HN];
    __shared__ float s_part[2][TILE_M];

    const int t    = threadIdx.x;
    const int lane = t & 31;
    const int wid  = t >> 5;
    const int wm   = wid & 3;    // 4 warps over M (32 rows each)
    const int wn   = wid >> 2;   // 2 warps over N (128 cols each)
    const int m0   = blockIdx.x * TILE_M;

    s_b1[t] = b1[t];
    s_w2[t] = W2[t];

    // ---- A gather: 2 threads per edge row, 16 floats (64B) each
    const int arow = t >> 1;
    const int aseg = t & 1;
    int mg = m0 + arow;
    int mc = (mg < E_EDGES) ? mg : (E_EDGES - 1);
    const float* psrc = emb_src + (size_t)eidx[mc] * HN;
    const float* pdst = emb_dst + (size_t)eidx[E_EDGES + mc] * HN;

    // ---- B copy coords: thread -> (k-row, 32-half segment)
    const int bkrow = t >> 3;
    const int bnseg = (t & 7) * 32;   // halves

    const uint32_t smb = smem_u32(sm);

    // ldmatrix lane addressing
    const uint32_t a_lrow = (uint32_t)(wm * 32 + (lane & 15));
    const uint32_t a_lcol = (uint32_t)((lane >> 4) * 8);             // halves
    const uint32_t b_lrow = (uint32_t)(lane & 15);
    const uint32_t b_lcol = (uint32_t)(wn * 128 + (lane >> 4) * 8);  // halves

    float acc[2][16][4];
    #pragma unroll
    for (int f = 0; f < 2; f++)
        #pragma unroll
        for (int g = 0; g < 16; g++)
            #pragma unroll
            for (int c = 0; c < 4; c++) acc[f][g][c] = 0.0f;

    float4 aR[4];

    auto a_issue = [&](int ch) {
        const int kbase = ch * KC;
        const float* rp = ((kbase < HN) ? (psrc + kbase) : (pdst + (kbase - HN)))
                          + aseg * 16;
        aR[0] = __ldg((const float4*)(rp + 0));
        aR[1] = __ldg((const float4*)(rp + 4));
        aR[2] = __ldg((const float4*)(rp + 8));
        aR[3] = __ldg((const float4*)(rp + 12));
    };
    auto a_store = [&](int stage) {
        float f[16] = {aR[0].x, aR[0].y, aR[0].z, aR[0].w,
                       aR[1].x, aR[1].y, aR[1].z, aR[1].w,
                       aR[2].x, aR[2].y, aR[2].z, aR[2].w,
                       aR[3].x, aR[3].y, aR[3].z, aR[3].w};
        alignas(16) __half hs[16];
        #pragma unroll
        for (int i = 0; i < 16; i++) hs[i] = __float2half_rn(f[i]);
        char* base = sm + stage * STAGE_B;
        uint32_t off = (uint32_t)arow * A_STRIDE_B + aseg * 32;
        *(uint4*)(base + SM_AHI + off)      = ((const uint4*)hs)[0];
        *(uint4*)(base + SM_AHI + off + 16) = ((const uint4*)hs)[1];
    };
    auto b_issue = [&](int ch, int stage) {
        const int kbase = ch * KC;
        const __half* gh = g_W1_hi + (size_t)(kbase + bkrow) * HN + bnseg;
        const __half* gl = g_W1_lo + (size_t)(kbase + bkrow) * HN + bnseg;
        uint32_t off = smb + stage * STAGE_B + (uint32_t)bkrow * B_STRIDE_B + bnseg * 2;
        #pragma unroll
        for (int q = 0; q < 4; q++) {
            cp_async16(off + SM_BHI + q * 16, gh + 8 * q);
            cp_async16(off + SM_BLO + q * 16, gl + 8 * q);
        }
    };
    auto compute = [&](int stage) {
        const uint32_t sbase = smb + stage * STAGE_B;
        #pragma unroll
        for (int ks = 0; ks < 2; ks++) {
            uint32_t ah[2][4];
            #pragma unroll
            for (int f = 0; f < 2; f++) {
                uint32_t aaddr = sbase + SM_AHI + (a_lrow + f * 16) * A_STRIDE_B
                               + (ks * 16 + a_lcol) * 2;
                ldsm_x4(aaddr, ah[f][0], ah[f][1], ah[f][2], ah[f][3]);
            }
            #pragma unroll
            for (int g4 = 0; g4 < 8; g4++) {
                uint32_t baddr = sbase + (ks * 16 + b_lrow) * B_STRIDE_B
                               + (b_lcol + g4 * 16) * 2;
                uint32_t bh0, bh1, bh2, bh3, bl0, bl1, bl2, bl3;
                ldsm_x4_t(baddr + SM_BHI, bh0, bh1, bh2, bh3);
                ldsm_x4_t(baddr + SM_BLO, bl0, bl1, bl2, bl3);
                #pragma unroll
                for (int f = 0; f < 2; f++) {
                    float* c0 = acc[f][g4 * 2];
                    float* c1 = acc[f][g4 * 2 + 1];
                    mma16816(c0, ah[f], bh0, bh1);   // hi*hi
                    mma16816(c0, ah[f], bl0, bl1);   // hi*lo  (== a_hi * w exactly-ish)
                    mma16816(c1, ah[f], bh2, bh3);
                    mma16816(c1, ah[f], bl2, bl3);
                }
            }
        }
    };

    // ---- prologue: fill stage 0
    a_issue(0);
    b_issue(0, 0);
    CP_COMMIT();
    a_store(0);
    CP_WAIT0();
    __syncthreads();

    // ---- 2-stage pipelined mainloop: one sync per chunk
    #pragma unroll 1
    for (int ch = 0; ch < NCHUNKS; ch++) {
        const int cur = ch & 1;
        const int nxt = cur ^ 1;
        if (ch + 1 < NCHUNKS) {
            a_issue(ch + 1);          // long-latency LDGs first
            b_issue(ch + 1, nxt);     // cp.async overlaps with MMAs below
            CP_COMMIT();
        }
        compute(cur);
        if (ch + 1 < NCHUNKS) {
            a_store(nxt);             // convert + STS after compute consumed cur
            CP_WAIT0();
        }
        __syncthreads();
    }

    // ---- fused epilogue: relu(acc + b1) * W2 -> per-row partial sums --------
    #pragma unroll
    for (int f = 0; f < 2; f++) {
        float s0 = 0.0f, s1 = 0.0f;
        #pragma unroll
        for (int g = 0; g < 16; g++) {
            const int col = wn * 128 + g * 8 + (lane & 3) * 2;
            const float b1a = s_b1[col], b1b = s_b1[col + 1];
            const float w2a = s_w2[col], w2b = s_w2[col + 1];
            float v;
            v = acc[f][g][0] + b1a; v = fmaxf(v, 0.0f); s0 = fmaf(v, w2a, s0);
            v = acc[f][g][1] + b1b; v = fmaxf(v, 0.0f); s0 = fmaf(v, w2b, s0);
            v = acc[f][g][2] + b1a; v = fmaxf(v, 0.0f); s1 = fmaf(v, w2a, s1);
            v = acc[f][g][3] + b1b; v = fmaxf(v, 0.0f); s1 = fmaf(v, w2b, s1);
        }
        s0 += __shfl_xor_sync(0xffffffffu, s0, 1);
        s0 += __shfl_xor_sync(0xffffffffu, s0, 2);
        s1 += __shfl_xor_sync(0xffffffffu, s1, 1);
        s1 += __shfl_xor_sync(0xffffffffu, s1, 2);
        if ((lane & 3) == 0) {
            const int r = wm * 32 + f * 16 + (lane >> 2);
            s_part[wn][r]     = s0;
            s_part[wn][r + 8] = s1;
        }
    }
    __syncthreads();

    if (t < TILE_M) {
        const int mgo = m0 + t;
        if (mgo < E_EDGES)
            out[mgo] = s_part[0][t] + s_part[1][t] + __ldg(b2);
    }
}

// ---------------- launch -----------------------------------------------------
extern "C" void kernel_launch(void* const* d_in, const int* in_sizes, int n_in,
                              void* d_out, int out_size) {
    const float* emb_src = (const float*)d_in[0];
    const float* emb_dst = (const float*)d_in[1];
    const int*   eidx    = (const int*)  d_in[2];
    const float* W1      = (const float*)d_in[3];
    const float* b1      = (const float*)d_in[4];
    const float* W2      = (const float*)d_in[5];
    const float* b2      = (const float*)d_in[6];
    float* out = (float*)d_out;

    static bool attr_done = false;
    if (!attr_done) {
        cudaFuncSetAttribute(linkpred_hmma_kernel,
                             cudaFuncAttributeMaxDynamicSharedMemorySize, SM_DYN_BYTES);
        attr_done = true;
    }

    prep_w1_kernel<<<(KDIM * HN + 255) / 256, 256>>>(W1);

    const int grid = (E_EDGES + TILE_M - 1) / TILE_M;   // 3907
    linkpred_hmma_kernel<<<grid, 256, SM_DYN_BYTES>>>(
        emb_src, emb_dst, eidx, b1, W2, b2, out);
}

// round 10
// speedup vs baseline: 3.9647x; 1.5594x over previous
#include <cuda_runtime.h>
#include <cuda_fp16.h>
#include <cstdint>

#define E_EDGES 500000
#define HN      256
#define KDIM    512
#define TILE_M  128
#define KC      32
#define NCHUNKS (KDIM / KC)    // 16

// ---------------- device-global scratch (compile-time, no runtime alloc) ----
__device__ __align__(16) __half g_W1_hi[KDIM * HN];   // [k][n], same layout as W1

// ---------------- prep: W1 fp32 -> fp16 --------------------------------------
__global__ void prep_w1_kernel(const float* __restrict__ W1) {
    int i = blockIdx.x * blockDim.x + threadIdx.x;
    if (i >= KDIM * HN) return;
    g_W1_hi[i] = __float2half_rn(W1[i]);
}

// ---------------- PTX helpers ------------------------------------------------
__device__ __forceinline__ uint32_t smem_u32(const void* p) {
    uint32_t a;
    asm("{ .reg .u64 t; cvta.to.shared.u64 t, %1; cvt.u32.u64 %0, t; }" : "=r"(a) : "l"(p));
    return a;
}
__device__ __forceinline__ void ldsm_x4(uint32_t addr, uint32_t& r0, uint32_t& r1,
                                        uint32_t& r2, uint32_t& r3) {
    asm volatile("ldmatrix.sync.aligned.m8n8.x4.shared.b16 {%0,%1,%2,%3}, [%4];"
                 : "=r"(r0), "=r"(r1), "=r"(r2), "=r"(r3) : "r"(addr));
}
__device__ __forceinline__ void ldsm_x4_t(uint32_t addr, uint32_t& r0, uint32_t& r1,
                                          uint32_t& r2, uint32_t& r3) {
    asm volatile("ldmatrix.sync.aligned.m8n8.x4.trans.shared.b16 {%0,%1,%2,%3}, [%4];"
                 : "=r"(r0), "=r"(r1), "=r"(r2), "=r"(r3) : "r"(addr));
}
__device__ __forceinline__ void mma16816(float* c, const uint32_t* a, uint32_t b0, uint32_t b1) {
    asm volatile(
        "mma.sync.aligned.m16n8k16.row.col.f32.f16.f16.f32 "
        "{%0,%1,%2,%3}, {%4,%5,%6,%7}, {%8,%9}, {%0,%1,%2,%3};"
        : "+f"(c[0]), "+f"(c[1]), "+f"(c[2]), "+f"(c[3])
        : "r"(a[0]), "r"(a[1]), "r"(a[2]), "r"(a[3]), "r"(b0), "r"(b1));
}
__device__ __forceinline__ void cp_async16(uint32_t saddr, const void* gptr) {
    asm volatile("cp.async.cg.shared.global [%0], [%1], 16;" :: "r"(saddr), "l"(gptr));
}
#define CP_COMMIT() asm volatile("cp.async.commit_group;" ::: "memory")
#define CP_WAIT0()  asm volatile("cp.async.wait_group 0;"  ::: "memory")

// ---------------- smem layout: 2 stages of (Ahi|Bhi) -------------------------
// As: [128][32h] stride 80B  -> 10240 B
// Bs: [32][256h] stride 528B -> 16896 B
#define A_STRIDE_B 80
#define B_STRIDE_B 528
#define SM_AHI 0
#define SM_BHI 10240
#define STAGE_B 27136
#define SM_DYN_BYTES (2 * STAGE_B)   // 54272

__global__ __launch_bounds__(256, 1)
void linkpred_hmma_kernel(const float* __restrict__ emb_src,
                          const float* __restrict__ emb_dst,
                          const int*   __restrict__ eidx,
                          const float* __restrict__ b1,
                          const float* __restrict__ W2,
                          const float* __restrict__ b2,
                          float*       __restrict__ out)
{
    extern __shared__ char sm[];
    __shared__ float s_b1[HN], s_w2[HN];
    __shared__ float s_part[4][TILE_M];

    const int t    = threadIdx.x;
    const int lane = t & 31;
    const int wid  = t >> 5;
    const int wm   = wid & 1;    // 2 warps over M (64 rows each)
    const int wn   = wid >> 1;   // 4 warps over N (64 cols each)
    const int m0   = blockIdx.x * TILE_M;

    s_b1[t] = b1[t];
    s_w2[t] = W2[t];

    // ---- A gather: 2 threads per edge row, 16 floats (64B) each
    const int arow = t >> 1;
    const int aseg = t & 1;
    int mg = m0 + arow;
    int mc = (mg < E_EDGES) ? mg : (E_EDGES - 1);
    const float* psrc = emb_src + (size_t)eidx[mc] * HN;
    const float* pdst = emb_dst + (size_t)eidx[E_EDGES + mc] * HN;

    // ---- B copy coords: thread -> (k-row, 32-half segment)
    const int bkrow = t >> 3;
    const int bnseg = (t & 7) * 32;   // halves

    const uint32_t smb = smem_u32(sm);

    // ldmatrix lane addressing
    const uint32_t a_lrow = (uint32_t)(wm * 64 + (lane & 15));
    const uint32_t a_lcol = (uint32_t)((lane >> 4) * 8);            // halves
    const uint32_t b_lrow = (uint32_t)(lane & 15);
    const uint32_t b_lcol = (uint32_t)(wn * 64 + (lane >> 4) * 8);  // halves

    // acc[f][g][c]: rows wm*64+f*16, cols wn*64+g*8
    float acc[4][8][4];
    #pragma unroll
    for (int f = 0; f < 4; f++)
        #pragma unroll
        for (int g = 0; g < 8; g++)
            #pragma unroll
            for (int c = 0; c < 4; c++) acc[f][g][c] = 0.0f;

    float4 aR[4];

    auto a_issue = [&](int ch) {
        const int kbase = ch * KC;
        const float* rp = ((kbase < HN) ? (psrc + kbase) : (pdst + (kbase - HN)))
                          + aseg * 16;
        aR[0] = __ldg((const float4*)(rp + 0));
        aR[1] = __ldg((const float4*)(rp + 4));
        aR[2] = __ldg((const float4*)(rp + 8));
        aR[3] = __ldg((const float4*)(rp + 12));
    };
    auto a_store = [&](int stage) {
        float f[16] = {aR[0].x, aR[0].y, aR[0].z, aR[0].w,
                       aR[1].x, aR[1].y, aR[1].z, aR[1].w,
                       aR[2].x, aR[2].y, aR[2].z, aR[2].w,
                       aR[3].x, aR[3].y, aR[3].z, aR[3].w};
        alignas(16) __half hs[16];
        #pragma unroll
        for (int i = 0; i < 16; i++) hs[i] = __float2half_rn(f[i]);
        char* base = sm + stage * STAGE_B;
        uint32_t off = (uint32_t)arow * A_STRIDE_B + aseg * 32;
        *(uint4*)(base + SM_AHI + off)      = ((const uint4*)hs)[0];
        *(uint4*)(base + SM_AHI + off + 16) = ((const uint4*)hs)[1];
    };
    auto b_issue = [&](int ch, int stage) {
        const int kbase = ch * KC;
        const __half* gh = g_W1_hi + (size_t)(kbase + bkrow) * HN + bnseg;
        uint32_t off = smb + stage * STAGE_B + SM_BHI
                     + (uint32_t)bkrow * B_STRIDE_B + bnseg * 2;
        #pragma unroll
        for (int q = 0; q < 4; q++)
            cp_async16(off + q * 16, gh + 8 * q);
    };
    auto compute = [&](int stage) {
        const uint32_t sbase = smb + stage * STAGE_B;
        #pragma unroll
        for (int ks = 0; ks < 2; ks++) {
            uint32_t ah[4][4];
            #pragma unroll
            for (int f = 0; f < 4; f++) {
                uint32_t aaddr = sbase + SM_AHI + (a_lrow + f * 16) * A_STRIDE_B
                               + (ks * 16 + a_lcol) * 2;
                ldsm_x4(aaddr, ah[f][0], ah[f][1], ah[f][2], ah[f][3]);
            }
            #pragma unroll
            for (int g4 = 0; g4 < 4; g4++) {
                uint32_t baddr = sbase + SM_BHI + (ks * 16 + b_lrow) * B_STRIDE_B
                               + (b_lcol + g4 * 16) * 2;
                uint32_t b0, b1r, b2r, b3;
                ldsm_x4_t(baddr, b0, b1r, b2r, b3);
                #pragma unroll
                for (int f = 0; f < 4; f++) {
                    mma16816(acc[f][g4 * 2],     ah[f], b0,  b1r);
                    mma16816(acc[f][g4 * 2 + 1], ah[f], b2r, b3);
                }
            }
        }
    };

    // ---- prologue: fill stage 0
    a_issue(0);
    b_issue(0, 0);
    CP_COMMIT();
    a_store(0);
    CP_WAIT0();
    __syncthreads();

    // ---- 2-stage pipelined mainloop: one sync per chunk
    #pragma unroll 1
    for (int ch = 0; ch < NCHUNKS; ch++) {
        const int cur = ch & 1;
        const int nxt = cur ^ 1;
        if (ch + 1 < NCHUNKS) {
            a_issue(ch + 1);          // long-latency LDGs first
            b_issue(ch + 1, nxt);     // cp.async overlaps with MMAs below
            CP_COMMIT();
        }
        compute(cur);
        if (ch + 1 < NCHUNKS) {
            a_store(nxt);             // convert + STS after compute consumed cur
            CP_WAIT0();
        }
        __syncthreads();
    }

    // ---- fused epilogue: relu(acc + b1) * W2 -> per-row partial sums --------
    #pragma unroll
    for (int f = 0; f < 4; f++) {
        float s0 = 0.0f, s1 = 0.0f;
        #pragma unroll
        for (int g = 0; g < 8; g++) {
            const int col = wn * 64 + g * 8 + (lane & 3) * 2;
            const float b1a = s_b1[col], b1b = s_b1[col + 1];
            const float w2a = s_w2[col], w2b = s_w2[col + 1];
            float v;
            v = acc[f][g][0] + b1a; v = fmaxf(v, 0.0f); s0 = fmaf(v, w2a, s0);
            v = acc[f][g][1] + b1b; v = fmaxf(v, 0.0f); s0 = fmaf(v, w2b, s0);
            v = acc[f][g][2] + b1a; v = fmaxf(v, 0.0f); s1 = fmaf(v, w2a, s1);
            v = acc[f][g][3] + b1b; v = fmaxf(v, 0.0f); s1 = fmaf(v, w2b, s1);
        }
        s0 += __shfl_xor_sync(0xffffffffu, s0, 1);
        s0 += __shfl_xor_sync(0xffffffffu, s0, 2);
        s1 += __shfl_xor_sync(0xffffffffu, s1, 1);
        s1 += __shfl_xor_sync(0xffffffffu, s1, 2);
        if ((lane & 3) == 0) {
            const int r = wm * 64 + f * 16 + (lane >> 2);
            s_part[wn][r]     = s0;
            s_part[wn][r + 8] = s1;
        }
    }
    __syncthreads();

    if (t < TILE_M) {
        const int mgo = m0 + t;
        if (mgo < E_EDGES)
            out[mgo] = (s_part[0][t] + s_part[1][t])
                     + (s_part[2][t] + s_part[3][t]) + __ldg(b2);
    }
}

// ---------------- launch -----------------------------------------------------
extern "C" void kernel_launch(void* const* d_in, const int* in_sizes, int n_in,
                              void* d_out, int out_size) {
    const float* emb_src = (const float*)d_in[0];
    const float* emb_dst = (const float*)d_in[1];
    const int*   eidx    = (const int*)  d_in[2];
    const float* W1      = (const float*)d_in[3];
    const float* b1      = (const float*)d_in[4];
    const float* W2      = (const float*)d_in[5];
    const float* b2      = (const float*)d_in[6];
    float* out = (float*)d_out;

    static bool attr_done = false;
    if (!attr_done) {
        cudaFuncSetAttribute(linkpred_hmma_kernel,
                             cudaFuncAttributeMaxDynamicSharedMemorySize, SM_DYN_BYTES);
        attr_done = true;
    }

    prep_w1_kernel<<<(KDIM * HN + 255) / 256, 256>>>(W1);

    const int grid = (E_EDGES + TILE_M - 1) / TILE_M;   // 3907
    linkpred_hmma_kernel<<<grid, 256, SM_DYN_BYTES>>>(
        emb_src, emb_dst, eidx, b1, W2, b2, out);
}

// round 11
// speedup vs baseline: 4.4191x; 1.1146x over previous
#include <cuda_runtime.h>
#include <cuda_fp16.h>
#include <cstdint>

#define E_EDGES 500000
#define HN      256
#define KDIM    512
#define TILE_M  128
#define KC      64
#define NCHUNKS (KDIM / KC)    // 8
#define THREADS 512

// ---------------- device-global scratch (compile-time, no runtime alloc) ----
__device__ __align__(16) __half g_W1_hi[KDIM * HN];   // [k][n], same layout as W1

// ---------------- prep: W1 fp32 -> fp16 --------------------------------------
__global__ void prep_w1_kernel(const float* __restrict__ W1) {
    int i = blockIdx.x * blockDim.x + threadIdx.x;
    if (i >= KDIM * HN) return;
    g_W1_hi[i] = __float2half_rn(W1[i]);
}

// ---------------- PTX helpers ------------------------------------------------
__device__ __forceinline__ uint32_t smem_u32(const void* p) {
    uint32_t a;
    asm("{ .reg .u64 t; cvta.to.shared.u64 t, %1; cvt.u32.u64 %0, t; }" : "=r"(a) : "l"(p));
    return a;
}
__device__ __forceinline__ void ldsm_x4(uint32_t addr, uint32_t& r0, uint32_t& r1,
                                        uint32_t& r2, uint32_t& r3) {
    asm volatile("ldmatrix.sync.aligned.m8n8.x4.shared.b16 {%0,%1,%2,%3}, [%4];"
                 : "=r"(r0), "=r"(r1), "=r"(r2), "=r"(r3) : "r"(addr));
}
__device__ __forceinline__ void ldsm_x4_t(uint32_t addr, uint32_t& r0, uint32_t& r1,
                                          uint32_t& r2, uint32_t& r3) {
    asm volatile("ldmatrix.sync.aligned.m8n8.x4.trans.shared.b16 {%0,%1,%2,%3}, [%4];"
                 : "=r"(r0), "=r"(r1), "=r"(r2), "=r"(r3) : "r"(addr));
}
__device__ __forceinline__ void mma16816(float* c, const uint32_t* a, uint32_t b0, uint32_t b1) {
    asm volatile(
        "mma.sync.aligned.m16n8k16.row.col.f32.f16.f16.f32 "
        "{%0,%1,%2,%3}, {%4,%5,%6,%7}, {%8,%9}, {%0,%1,%2,%3};"
        : "+f"(c[0]), "+f"(c[1]), "+f"(c[2]), "+f"(c[3])
        : "r"(a[0]), "r"(a[1]), "r"(a[2]), "r"(a[3]), "r"(b0), "r"(b1));
}
__device__ __forceinline__ void cp_async16(uint32_t saddr, const void* gptr) {
    asm volatile("cp.async.cg.shared.global [%0], [%1], 16;" :: "r"(saddr), "l"(gptr));
}
#define CP_COMMIT() asm volatile("cp.async.commit_group;" ::: "memory")
#define CP_WAIT0()  asm volatile("cp.async.wait_group 0;"  ::: "memory")

// ---------------- smem layout: 2 stages of (A[2 sub]|B) ----------------------
// A sub: [128][32h] stride 80B -> 10240 B  (2 subs = k 0-31, 32-63 of chunk)
// B: [64][256h] stride 528B -> 33792 B
#define A_STRIDE_B 80
#define A_SUB_B    10240
#define B_STRIDE_B 528
#define SM_AHI 0
#define SM_BHI 20480
#define STAGE_B 54272
#define SM_DYN_BYTES (2 * STAGE_B)   // 108544

__global__ __launch_bounds__(THREADS, 1)
void linkpred_hmma_kernel(const float* __restrict__ emb_src,
                          const float* __restrict__ emb_dst,
                          const int*   __restrict__ eidx,
                          const float* __restrict__ b1,
                          const float* __restrict__ W2,
                          const float* __restrict__ b2,
                          float*       __restrict__ out)
{
    extern __shared__ char sm[];
    __shared__ float s_b1[HN], s_w2[HN];
    __shared__ float s_part[4][TILE_M];

    const int t    = threadIdx.x;
    const int lane = t & 31;
    const int wid  = t >> 5;
    const int wm   = wid & 3;    // 4 warps over M (32 rows each)
    const int wn   = wid >> 2;   // 4 warps over N (64 cols each)
    const int m0   = blockIdx.x * TILE_M;

    if (t < HN) { s_b1[t] = b1[t]; s_w2[t] = W2[t]; }

    // ---- A gather: 4 threads per edge row, 16 floats (64B) each
    const int arow = t >> 2;
    const int aseg = t & 3;
    int mg = m0 + arow;
    int mc = (mg < E_EDGES) ? mg : (E_EDGES - 1);
    const float* psrc = emb_src + (size_t)eidx[mc] * HN;
    const float* pdst = emb_dst + (size_t)eidx[E_EDGES + mc] * HN;

    // ---- B copy coords: thread -> (k-row, 32-half segment)
    const int bkrow = t >> 3;          // 0..63
    const int bnseg = (t & 7) * 32;    // halves

    const uint32_t smb = smem_u32(sm);

    // ldmatrix lane addressing
    const uint32_t a_lrow = (uint32_t)(wm * 32 + (lane & 15));
    const uint32_t a_lcol = (uint32_t)((lane >> 4) * 8);            // halves
    const uint32_t b_lrow = (uint32_t)(lane & 15);
    const uint32_t b_lcol = (uint32_t)(wn * 64 + (lane >> 4) * 8);  // halves

    // acc[f][g][c]: rows wm*32 + f*16, cols wn*64 + g*8
    float acc[2][8][4];
    #pragma unroll
    for (int f = 0; f < 2; f++)
        #pragma unroll
        for (int g = 0; g < 8; g++)
            #pragma unroll
            for (int c = 0; c < 4; c++) acc[f][g][c] = 0.0f;

    float4 aR[4];

    auto a_issue = [&](int ch) {
        const int kbase = ch * KC;   // chunks 0-3: src, 4-7: dst (KC=64 divides 256)
        const float* rp = ((kbase < HN) ? (psrc + kbase) : (pdst + (kbase - HN)))
                          + aseg * 16;
        aR[0] = __ldg((const float4*)(rp + 0));
        aR[1] = __ldg((const float4*)(rp + 4));
        aR[2] = __ldg((const float4*)(rp + 8));
        aR[3] = __ldg((const float4*)(rp + 12));
    };
    auto a_store = [&](int stage) {
        float f[16] = {aR[0].x, aR[0].y, aR[0].z, aR[0].w,
                       aR[1].x, aR[1].y, aR[1].z, aR[1].w,
                       aR[2].x, aR[2].y, aR[2].z, aR[2].w,
                       aR[3].x, aR[3].y, aR[3].z, aR[3].w};
        alignas(16) __half hs[16];
        #pragma unroll
        for (int i = 0; i < 16; i++) hs[i] = __float2half_rn(f[i]);
        // sub-tile: aseg 0,1 -> sub 0 (k 0-31); aseg 2,3 -> sub 1 (k 32-63)
        char* base = sm + stage * STAGE_B + SM_AHI + (aseg >> 1) * A_SUB_B;
        uint32_t off = (uint32_t)arow * A_STRIDE_B + (aseg & 1) * 32;
        *(uint4*)(base + off)      = ((const uint4*)hs)[0];
        *(uint4*)(base + off + 16) = ((const uint4*)hs)[1];
    };
    auto b_issue = [&](int ch, int stage) {
        const int kbase = ch * KC;
        const __half* gh = g_W1_hi + (size_t)(kbase + bkrow) * HN + bnseg;
        uint32_t off = smb + stage * STAGE_B + SM_BHI
                     + (uint32_t)bkrow * B_STRIDE_B + bnseg * 2;
        #pragma unroll
        for (int q = 0; q < 4; q++)
            cp_async16(off + q * 16, gh + 8 * q);
    };
    auto compute = [&](int stage) {
        const uint32_t sbase = smb + stage * STAGE_B;
        #pragma unroll
        for (int ks = 0; ks < 4; ks++) {
            const uint32_t asub = sbase + SM_AHI + (ks >> 1) * A_SUB_B;
            const uint32_t ksi  = (uint32_t)(ks & 1);
            uint32_t ah[2][4];
            #pragma unroll
            for (int f = 0; f < 2; f++) {
                uint32_t aaddr = asub + (a_lrow + f * 16) * A_STRIDE_B
                               + (ksi * 16 + a_lcol) * 2;
                ldsm_x4(aaddr, ah[f][0], ah[f][1], ah[f][2], ah[f][3]);
            }
            #pragma unroll
            for (int g4 = 0; g4 < 4; g4++) {
                uint32_t baddr = sbase + SM_BHI + (ks * 16 + b_lrow) * B_STRIDE_B
                               + (b_lcol + g4 * 16) * 2;
                uint32_t b0, b1r, b2r, b3;
                ldsm_x4_t(baddr, b0, b1r, b2r, b3);
                #pragma unroll
                for (int f = 0; f < 2; f++) {
                    mma16816(acc[f][g4 * 2],     ah[f], b0,  b1r);
                    mma16816(acc[f][g4 * 2 + 1], ah[f], b2r, b3);
                }
            }
        }
    };

    // ---- prologue: fill stage 0
    a_issue(0);
    b_issue(0, 0);
    CP_COMMIT();
    a_store(0);
    CP_WAIT0();
    __syncthreads();

    // ---- 2-stage pipelined mainloop: one sync per chunk
    #pragma unroll 1
    for (int ch = 0; ch < NCHUNKS; ch++) {
        const int cur = ch & 1;
        const int nxt = cur ^ 1;
        if (ch + 1 < NCHUNKS) {
            a_issue(ch + 1);          // long-latency LDGs first
            b_issue(ch + 1, nxt);     // cp.async overlaps with MMAs below
            CP_COMMIT();
        }
        compute(cur);
        if (ch + 1 < NCHUNKS) {
            a_store(nxt);             // convert + STS after compute consumed cur
            CP_WAIT0();
        }
        __syncthreads();
    }

    // ---- fused epilogue: relu(acc + b1) * W2 -> per-row partial sums --------
    #pragma unroll
    for (int f = 0; f < 2; f++) {
        float s0 = 0.0f, s1 = 0.0f;
        #pragma unroll
        for (int g = 0; g < 8; g++) {
            const int col = wn * 64 + g * 8 + (lane & 3) * 2;
            const float b1a = s_b1[col], b1b = s_b1[col + 1];
            const float w2a = s_w2[col], w2b = s_w2[col + 1];
            float v;
            v = acc[f][g][0] + b1a; v = fmaxf(v, 0.0f); s0 = fmaf(v, w2a, s0);
            v = acc[f][g][1] + b1b; v = fmaxf(v, 0.0f); s0 = fmaf(v, w2b, s0);
            v = acc[f][g][2] + b1a; v = fmaxf(v, 0.0f); s1 = fmaf(v, w2a, s1);
            v = acc[f][g][3] + b1b; v = fmaxf(v, 0.0f); s1 = fmaf(v, w2b, s1);
        }
        s0 += __shfl_xor_sync(0xffffffffu, s0, 1);
        s0 += __shfl_xor_sync(0xffffffffu, s0, 2);
        s1 += __shfl_xor_sync(0xffffffffu, s1, 1);
        s1 += __shfl_xor_sync(0xffffffffu, s1, 2);
        if ((lane & 3) == 0) {
            const int r = wm * 32 + f * 16 + (lane >> 2);
            // accumulate across the 4 N-warps via 4 separate slabs
            s_part[wn][r]     = s0;
            s_part[wn][r + 8] = s1;
        }
    }
    __syncthreads();

    if (t < TILE_M) {
        const int mgo = m0 + t;
        if (mgo < E_EDGES)
            out[mgo] = (s_part[0][t] + s_part[1][t])
                     + (s_part[2][t] + s_part[3][t]) + __ldg(b2);
    }
}

// ---------------- launch -----------------------------------------------------
extern "C" void kernel_launch(void* const* d_in, const int* in_sizes, int n_in,
                              void* d_out, int out_size) {
    const float* emb_src = (const float*)d_in[0];
    const float* emb_dst = (const float*)d_in[1];
    const int*   eidx    = (const int*)  d_in[2];
    const float* W1      = (const float*)d_in[3];
    const float* b1      = (const float*)d_in[4];
    const float* W2      = (const float*)d_in[5];
    const float* b2      = (const float*)d_in[6];
    float* out = (float*)d_out;

    static bool attr_done = false;
    if (!attr_done) {
        cudaFuncSetAttribute(linkpred_hmma_kernel,
                             cudaFuncAttributeMaxDynamicSharedMemorySize, SM_DYN_BYTES);
        attr_done = true;
    }

    prep_w1_kernel<<<(KDIM * HN + 255) / 256, 256>>>(W1);

    const int grid = (E_EDGES + TILE_M - 1) / TILE_M;   // 3907
    linkpred_hmma_kernel<<<grid, THREADS, SM_DYN_BYTES>>>(
        emb_src, emb_dst, eidx, b1, W2, b2, out);
}

// round 12
// speedup vs baseline: 4.6429x; 1.0507x over previous
#include <cuda_runtime.h>
#include <cuda_fp16.h>
#include <cstdint>

#define E_EDGES 500000
#define HN      256
#define KDIM    512
#define TILE_M  128
#define KC      64
#define NCHUNKS (KDIM / KC)    // 8
#define THREADS 512

// ---------------- device-global scratch (compile-time, no runtime alloc) ----
__device__ __align__(16) __half g_W1_hi[KDIM * HN];   // [k][n], same layout as W1

// ---------------- prep: W1 fp32 -> fp16 --------------------------------------
__global__ void prep_w1_kernel(const float* __restrict__ W1) {
    int i = blockIdx.x * blockDim.x + threadIdx.x;
    if (i >= KDIM * HN) return;
    g_W1_hi[i] = __float2half_rn(W1[i]);
}

// ---------------- PTX helpers ------------------------------------------------
__device__ __forceinline__ uint32_t smem_u32(const void* p) {
    uint32_t a;
    asm("{ .reg .u64 t; cvta.to.shared.u64 t, %1; cvt.u32.u64 %0, t; }" : "=r"(a) : "l"(p));
    return a;
}
__device__ __forceinline__ void ldsm_x4(uint32_t addr, uint32_t& r0, uint32_t& r1,
                                        uint32_t& r2, uint32_t& r3) {
    asm volatile("ldmatrix.sync.aligned.m8n8.x4.shared.b16 {%0,%1,%2,%3}, [%4];"
                 : "=r"(r0), "=r"(r1), "=r"(r2), "=r"(r3) : "r"(addr));
}
__device__ __forceinline__ void ldsm_x4_t(uint32_t addr, uint32_t& r0, uint32_t& r1,
                                          uint32_t& r2, uint32_t& r3) {
    asm volatile("ldmatrix.sync.aligned.m8n8.x4.trans.shared.b16 {%0,%1,%2,%3}, [%4];"
                 : "=r"(r0), "=r"(r1), "=r"(r2), "=r"(r3) : "r"(addr));
}
__device__ __forceinline__ void mma16816(float* c, const uint32_t* a, uint32_t b0, uint32_t b1) {
    asm volatile(
        "mma.sync.aligned.m16n8k16.row.col.f32.f16.f16.f32 "
        "{%0,%1,%2,%3}, {%4,%5,%6,%7}, {%8,%9}, {%0,%1,%2,%3};"
        : "+f"(c[0]), "+f"(c[1]), "+f"(c[2]), "+f"(c[3])
        : "r"(a[0]), "r"(a[1]), "r"(a[2]), "r"(a[3]), "r"(b0), "r"(b1));
}
__device__ __forceinline__ void cp_async16(uint32_t saddr, const void* gptr) {
    asm volatile("cp.async.cg.shared.global [%0], [%1], 16;" :: "r"(saddr), "l"(gptr));
}
#define CP_COMMIT() asm volatile("cp.async.commit_group;" ::: "memory")
#define CP_WAIT0()  asm volatile("cp.async.wait_group 0;"  ::: "memory")
#define CP_WAIT1()  asm volatile("cp.async.wait_group 1;"  ::: "memory")

// ---------------- smem layout ------------------------------------------------
// A: 2 stages x 2 subs x [128][32h] stride 80B = 2 x 20480
// B: 3 stages x [64][256h] stride 528B = 3 x 33792
#define A_STRIDE_B 80
#define A_SUB_B    10240
#define A_STAGE_B  20480
#define B_STRIDE_B 528
#define B_STAGE_B  33792
#define SM_B       40960
#define SM_DYN_BYTES (SM_B + 3 * B_STAGE_B)   // 142336

__global__ __launch_bounds__(THREADS, 1)
void linkpred_hmma_kernel(const float* __restrict__ emb_src,
                          const float* __restrict__ emb_dst,
                          const int*   __restrict__ eidx,
                          const float* __restrict__ b1,
                          const float* __restrict__ W2,
                          const float* __restrict__ b2,
                          float*       __restrict__ out)
{
    extern __shared__ char sm[];
    __shared__ float s_b1[HN], s_w2[HN];
    __shared__ float s_part[4][TILE_M];

    const int t    = threadIdx.x;
    const int lane = t & 31;
    const int wid  = t >> 5;
    const int wm   = wid & 3;    // 4 warps over M (32 rows each)
    const int wn   = wid >> 2;   // 4 warps over N (64 cols each)
    const int m0   = blockIdx.x * TILE_M;

    if (t < HN) { s_b1[t] = b1[t]; s_w2[t] = W2[t]; }

    // ---- A gather: 4 threads per edge row, 16 floats (64B) each
    const int arow = t >> 2;
    const int aseg = t & 3;
    int mg = m0 + arow;
    int mc = (mg < E_EDGES) ? mg : (E_EDGES - 1);
    const float* psrc = emb_src + (size_t)eidx[mc] * HN;
    const float* pdst = emb_dst + (size_t)eidx[E_EDGES + mc] * HN;

    // ---- B copy coords: thread -> (k-row, 32-half segment)
    const int bkrow = t >> 3;          // 0..63
    const int bnseg = (t & 7) * 32;    // halves

    const uint32_t smb = smem_u32(sm);

    // ldmatrix lane addressing
    const uint32_t a_lrow = (uint32_t)(wm * 32 + (lane & 15));
    const uint32_t a_lcol = (uint32_t)((lane >> 4) * 8);            // halves
    const uint32_t b_lrow = (uint32_t)(lane & 15);
    const uint32_t b_lcol = (uint32_t)(wn * 64 + (lane >> 4) * 8);  // halves

    // acc[f][g][c]: rows wm*32 + f*16, cols wn*64 + g*8
    float acc[2][8][4];
    #pragma unroll
    for (int f = 0; f < 2; f++)
        #pragma unroll
        for (int g = 0; g < 8; g++)
            #pragma unroll
            for (int c = 0; c < 4; c++) acc[f][g][c] = 0.0f;

    float4 aR[4];

    auto a_issue = [&](int ch) {
        const int kbase = ch * KC;   // chunks 0-3: src, 4-7: dst
        const float* rp = ((kbase < HN) ? (psrc + kbase) : (pdst + (kbase - HN)))
                          + aseg * 16;
        aR[0] = __ldg((const float4*)(rp + 0));
        aR[1] = __ldg((const float4*)(rp + 4));
        aR[2] = __ldg((const float4*)(rp + 8));
        aR[3] = __ldg((const float4*)(rp + 12));
    };
    auto a_store = [&](int stageA) {
        float f[16] = {aR[0].x, aR[0].y, aR[0].z, aR[0].w,
                       aR[1].x, aR[1].y, aR[1].z, aR[1].w,
                       aR[2].x, aR[2].y, aR[2].z, aR[2].w,
                       aR[3].x, aR[3].y, aR[3].z, aR[3].w};
        alignas(16) __half hs[16];
        #pragma unroll
        for (int i = 0; i < 16; i++) hs[i] = __float2half_rn(f[i]);
        // sub-tile: aseg 0,1 -> k 0-31; aseg 2,3 -> k 32-63
        char* base = sm + stageA * A_STAGE_B + (aseg >> 1) * A_SUB_B;
        uint32_t off = (uint32_t)arow * A_STRIDE_B + (aseg & 1) * 32;
        *(uint4*)(base + off)      = ((const uint4*)hs)[0];
        *(uint4*)(base + off + 16) = ((const uint4*)hs)[1];
    };
    auto b_issue = [&](int ch, int stageB) {
        const int kbase = ch * KC;
        const __half* gh = g_W1_hi + (size_t)(kbase + bkrow) * HN + bnseg;
        uint32_t off = smb + SM_B + stageB * B_STAGE_B
                     + (uint32_t)bkrow * B_STRIDE_B + bnseg * 2;
        #pragma unroll
        for (int q = 0; q < 4; q++)
            cp_async16(off + q * 16, gh + 8 * q);
    };
    auto compute = [&](int stageA, int stageB) {
        const uint32_t abase = smb + stageA * A_STAGE_B;
        const uint32_t bbase = smb + SM_B + stageB * B_STAGE_B;
        #pragma unroll
        for (int ks = 0; ks < 4; ks++) {
            const uint32_t asub = abase + (ks >> 1) * A_SUB_B;
            const uint32_t ksi  = (uint32_t)(ks & 1);
            uint32_t ah[2][4];
            #pragma unroll
            for (int f = 0; f < 2; f++) {
                uint32_t aaddr = asub + (a_lrow + f * 16) * A_STRIDE_B
                               + (ksi * 16 + a_lcol) * 2;
                ldsm_x4(aaddr, ah[f][0], ah[f][1], ah[f][2], ah[f][3]);
            }
            #pragma unroll
            for (int g4 = 0; g4 < 4; g4++) {
                uint32_t baddr = bbase + (ks * 16 + b_lrow) * B_STRIDE_B
                               + (b_lcol + g4 * 16) * 2;
                uint32_t b0, b1r, b2r, b3;
                ldsm_x4_t(baddr, b0, b1r, b2r, b3);
                #pragma unroll
                for (int f = 0; f < 2; f++) {
                    mma16816(acc[f][g4 * 2],     ah[f], b0,  b1r);
                    mma16816(acc[f][g4 * 2 + 1], ah[f], b2r, b3);
                }
            }
        }
    };

    // ---- prologue: A chunk0 -> stage0; B chunks 0,1 -> stages 0,1
    a_issue(0);
    b_issue(0, 0);
    CP_COMMIT();
    b_issue(1, 1);
    CP_COMMIT();
    a_store(0);
    CP_WAIT1();          // group for chunk0 done; chunk1 may fly
    __syncthreads();

    // ---- mainloop: B 3-stage ring, A 2-stage, one sync per chunk
    #pragma unroll 1
    for (int ch = 0; ch < NCHUNKS; ch++) {
        const int aCur = ch & 1;
        const int bCur = ch % 3;
        if (ch + 1 < NCHUNKS) a_issue(ch + 1);
        if (ch + 2 < NCHUNKS) {
            b_issue(ch + 2, (ch + 2) % 3);
            CP_COMMIT();
        }
        compute(aCur, bCur);
        if (ch + 1 < NCHUNKS) {
            a_store(aCur ^ 1);
            if (ch + 2 < NCHUNKS) CP_WAIT1();   // chunk ch+1's B must be done
            else                  CP_WAIT0();   // last pending group
        }
        __syncthreads();
    }

    // ---- fused epilogue: relu(acc + b1) * W2 -> per-row partial sums --------
    #pragma unroll
    for (int f = 0; f < 2; f++) {
        float s0 = 0.0f, s1 = 0.0f;
        #pragma unroll
        for (int g = 0; g < 8; g++) {
            const int col = wn * 64 + g * 8 + (lane & 3) * 2;
            const float b1a = s_b1[col], b1b = s_b1[col + 1];
            const float w2a = s_w2[col], w2b = s_w2[col + 1];
            float v;
            v = acc[f][g][0] + b1a; v = fmaxf(v, 0.0f); s0 = fmaf(v, w2a, s0);
            v = acc[f][g][1] + b1b; v = fmaxf(v, 0.0f); s0 = fmaf(v, w2b, s0);
            v = acc[f][g][2] + b1a; v = fmaxf(v, 0.0f); s1 = fmaf(v, w2a, s1);
            v = acc[f][g][3] + b1b; v = fmaxf(v, 0.0f); s1 = fmaf(v, w2b, s1);
        }
        s0 += __shfl_xor_sync(0xffffffffu, s0, 1);
        s0 += __shfl_xor_sync(0xffffffffu, s0, 2);
        s1 += __shfl_xor_sync(0xffffffffu, s1, 1);
        s1 += __shfl_xor_sync(0xffffffffu, s1, 2);
        if ((lane & 3) == 0) {
            const int r = wm * 32 + f * 16 + (lane >> 2);
            s_part[wn][r]     = s0;
            s_part[wn][r + 8] = s1;
        }
    }
    __syncthreads();

    if (t < TILE_M) {
        const int mgo = m0 + t;
        if (mgo < E_EDGES)
            out[mgo] = (s_part[0][t] + s_part[1][t])
                     + (s_part[2][t] + s_part[3][t]) + __ldg(b2);
    }
}

// ---------------- launch -----------------------------------------------------
extern "C" void kernel_launch(void* const* d_in, const int* in_sizes, int n_in,
                              void* d_out, int out_size) {
    const float* emb_src = (const float*)d_in[0];
    const float* emb_dst = (const float*)d_in[1];
    const int*   eidx    = (const int*)  d_in[2];
    const float* W1      = (const float*)d_in[3];
    const float* b1      = (const float*)d_in[4];
    const float* W2      = (const float*)d_in[5];
    const float* b2      = (const float*)d_in[6];
    float* out = (float*)d_out;

    static bool attr_done = false;
    if (!attr_done) {
        cudaFuncSetAttribute(linkpred_hmma_kernel,
                             cudaFuncAttributeMaxDynamicSharedMemorySize, SM_DYN_BYTES);
        attr_done = true;
    }

    prep_w1_kernel<<<(KDIM * HN + 255) / 256, 256>>>(W1);

    const int grid = (E_EDGES + TILE_M - 1) / TILE_M;   // 3907
    linkpred_hmma_kernel<<<grid, THREADS, SM_DYN_BYTES>>>(
        emb_src, emb_dst, eidx, b1, W2, b2, out);
}